// round 5
// baseline (speedup 1.0000x reference)
#include <cuda_runtime.h>
#include <cstdint>

// Problem: B=16, C=3, H=W=1024 -> 48 planes of 1024x1024 8-bit values,
// 10 iterations of (row circular shift by parity) -> (col circular shift by
// parity) -> (XOR with key masks).
//
// State packed 4 bytes/word: SP = normal layout [plane][row i][word w] (byte k
// of word w = column 4w+k). TP = transposed layout [plane][col j][word v]
// (byte k of word v = row 4v+k).
//
// Per iteration:
//   k_row: SP -> TP  (row shift + transpose), accumulates column parities (cp)
//   k_col: TP -> SP  (col shift + transpose back + XOR), accumulates row
//          parities (rp) for the next iteration.

#define PLANES 48
#define HH 1024
#define WPR 256            // 32-bit words per 1024-px row
#define NPW (PLANES * HH)  // parity-accumulator entries (one per plane-row/col)

__device__ uint32_t g_SP[PLANES * HH * WPR];   // 48 MB, normal layout
__device__ uint32_t g_TP[PLANES * HH * WPR];   // 48 MB, transposed layout
__device__ uint32_t g_rp[2][NPW];              // row-parity XOR accumulators
__device__ uint32_t g_cp[2][NPW];              // col-parity XOR accumulators
__device__ int      g_sr[HH];                  // (-kr) mod 1024
__device__ int      g_sc[HH];                  // (-kc) mod 1024
__device__ uint32_t g_krw[HH];                 // packed kr xor mask per row
__device__ uint32_t g_kcw[2][WPR];             // packed kc xor mask, [row parity][word]

__device__ __forceinline__ int fold_par(uint32_t v) {
    v ^= v >> 16; v ^= v >> 8; return (int)(v & 1u);
}
// Bank-conflict-free swizzled smem index for a 128-row x 32-word tile.
// Phase-2 reads rows (4*lane + k) at fixed word -> bank = (5*lane + k + w) % 32,
// distinct across lanes (gcd(5,32)=1). Phase-1 row-major writes also clean.
__device__ __forceinline__ int smidx(int r, int w) {
    return r * 33 + ((w + (r >> 2)) & 31);
}
__device__ __forceinline__ uint32_t warp_xor(uint32_t v) {
#if __CUDA_ARCH__ >= 800
    return __reduce_xor_sync(0xffffffffu, v);
#else
    for (int o = 16; o; o >>= 1) v ^= __shfl_xor_sync(0xffffffffu, v, o);
    return v;
#endif
}

// ---------------------------------------------------------------------------
// Init: clear parity accumulators, build shift amounts and XOR mask tables.
// ---------------------------------------------------------------------------
__global__ void k_init(const int* __restrict__ kr, const int* __restrict__ kc) {
    int gid = blockIdx.x * 1024 + threadIdx.x;
    if (gid < NPW) {
        g_rp[0][gid] = 0u; g_rp[1][gid] = 0u;
        g_cp[0][gid] = 0u; g_cp[1][gid] = 0u;
    }
    if (blockIdx.x == 0) {
        int t = threadIdx.x;                    // 0..1023
        int kri = kr[t], krr = kr[1023 - t];
        g_sr[t] = (1024 - kri) & 1023;          // (-kr) mod 1024, kr in [0,256)
        g_sc[t] = (1024 - kc[t]) & 1023;
        // xor_rows[i][j]: j even -> kr[i], j odd -> kr[1023-i]
        g_krw[t] = (uint32_t)kri | ((uint32_t)krr << 8) |
                   ((uint32_t)kri << 16) | ((uint32_t)krr << 24);
        if (t < WPR) {
            // xor_cols[i][j]: i even -> kc[j], i odd -> kc[1023-j]
            uint32_t a = (uint32_t)kc[4 * t]     | ((uint32_t)kc[4 * t + 1] << 8) |
                         ((uint32_t)kc[4 * t + 2] << 16) | ((uint32_t)kc[4 * t + 3] << 24);
            uint32_t b = (uint32_t)kc[1023 - 4 * t]       | ((uint32_t)kc[1023 - 4 * t - 1] << 8) |
                         ((uint32_t)kc[1023 - 4 * t - 2] << 16) | ((uint32_t)kc[1023 - 4 * t - 3] << 24);
            g_kcw[0][t] = a;
            g_kcw[1][t] = b;
        }
    }
}

// ---------------------------------------------------------------------------
// Pack: float -> packed bytes, and initial row parities (Malpha for iter 0).
// ---------------------------------------------------------------------------
__global__ void __launch_bounds__(256) k_pack(const float* __restrict__ x) {
    int idx = blockIdx.x * 256 + threadIdx.x;         // word id, < 48*1024*256
    float4 f = reinterpret_cast<const float4*>(x)[idx];
    uint32_t b0 = (uint32_t)__float2int_rz(f.x * 255.0f);
    uint32_t b1 = (uint32_t)__float2int_rz(f.y * 255.0f);
    uint32_t b2 = (uint32_t)__float2int_rz(f.z * 255.0f);
    uint32_t b3 = (uint32_t)__float2int_rz(f.w * 255.0f);
    uint32_t w = b0 | (b1 << 8) | (b2 << 16) | (b3 << 24);
    g_SP[idx] = w;
    // warp spans 32 aligned words of one row (256 words/row)
    uint32_t red = warp_xor(w);
    if ((threadIdx.x & 31) == 0) atomicXor(&g_rp[0][idx >> 8], red);
}

// ---------------------------------------------------------------------------
// k_row: row shift (Malpha: 0 -> left by s_r, else right) + transpose SP->TP.
// Accumulates column parities into g_cp[t&1]. Clears next-iteration buffers.
// ---------------------------------------------------------------------------
__global__ void __launch_bounds__(256) k_row(int t, const int* __restrict__ iters) {
    if (t >= *iters) return;
    __shared__ uint32_t sm[128 * 33];
    const int tb = t & 1, nb = tb ^ 1;

    // clear next-iteration accumulators (not used by this kernel or k_col(t) reads)
    int gid = ((blockIdx.z * gridDim.y + blockIdx.y) * gridDim.x + blockIdx.x) * 256 + threadIdx.x;
    if (gid < NPW) { g_cp[nb][gid] = 0u; g_rp[nb][gid] = 0u; }

    const int p = blockIdx.z;
    const int i0 = blockIdx.y * 128, j0 = blockIdx.x * 128;
    const int wb = j0 >> 2, vb = i0 >> 2;
    const int warp = threadIdx.x >> 5, lane = threadIdx.x & 31;

    // Phase 1: load 128 rows x 128 cols, row-shifted, into smem tile
#pragma unroll 4
    for (int r = 0; r < 16; ++r) {
        int ii = warp * 16 + r;
        int i = i0 + ii;
        int m = fold_par(g_rp[tb][p * 1024 + i]);        // Malpha
        int s = g_sr[i];
        int e = m ? ((1024 - s) & 1023) : s;             // new[j] = old[(j+e)%W]
        int pos0 = ((wb << 2) + e) & 1023;
        int a = pos0 & 3, bw = pos0 >> 2;
        const uint32_t* row = g_SP + (p * 1024 + i) * WPR;
        uint32_t u0 = row[(bw + lane) & 255];
        uint32_t u1 = row[(bw + lane + 1) & 255];
        sm[smidx(ii, lane)] = __funnelshift_r(u0, u1, a * 8);
    }
    __syncthreads();

    // Phase 2: transpose out to TP; accumulate column parities
#pragma unroll 4
    for (int r = 0; r < 16; ++r) {
        int jj = warp * 16 + r;
        int wl = jj >> 2, b = jj & 3;
        uint32_t sel = (uint32_t)b | ((uint32_t)(b + 4) << 4);
        uint32_t w0 = sm[smidx(4 * lane + 0, wl)];
        uint32_t w1 = sm[smidx(4 * lane + 1, wl)];
        uint32_t w2 = sm[smidx(4 * lane + 2, wl)];
        uint32_t w3 = sm[smidx(4 * lane + 3, wl)];
        uint32_t t01 = __byte_perm(w0, w1, sel);
        uint32_t t23 = __byte_perm(w2, w3, sel);
        uint32_t out = __byte_perm(t01, t23, 0x5410);
        int j = j0 + jj;
        g_TP[(p * 1024 + j) * WPR + vb + lane] = out;
        uint32_t red = warp_xor(out);
        if (lane == 0) atomicXor(&g_cp[tb][p * 1024 + j], red);
    }
}

// ---------------------------------------------------------------------------
// k_col: col shift (Mbeta: 1 -> up by s_c, else down) on TP + transpose back
// to SP + XOR masks. Accumulates next row parities into g_rp[(t+1)&1].
// ---------------------------------------------------------------------------
__global__ void __launch_bounds__(256) k_col(int t, const int* __restrict__ iters) {
    if (t >= *iters) return;
    __shared__ uint32_t sm[128 * 33];
    const int tb = t & 1, nb = tb ^ 1;
    const int p = blockIdx.z;
    const int i0 = blockIdx.y * 128, j0 = blockIdx.x * 128;
    const int wb = j0 >> 2, ib = i0 >> 2;
    const int warp = threadIdx.x >> 5, lane = threadIdx.x & 31;

    // Phase 1: load 128 transposed-rows (cols j), col-shifted, into smem tile
#pragma unroll 4
    for (int r = 0; r < 16; ++r) {
        int jj = warp * 16 + r;
        int j = j0 + jj;
        int mb = fold_par(g_cp[tb][p * 1024 + j]);       // Mbeta
        int s = g_sc[j];
        int f = (mb == 1) ? s : ((1024 - s) & 1023);     // new[i] = old[(i+f)%H]
        int pos0 = ((ib << 2) + f) & 1023;
        int a = pos0 & 3, bw = pos0 >> 2;
        const uint32_t* row = g_TP + (p * 1024 + j) * WPR;
        uint32_t u0 = row[(bw + lane) & 255];
        uint32_t u1 = row[(bw + lane + 1) & 255];
        sm[smidx(jj, lane)] = __funnelshift_r(u0, u1, a * 8);
    }
    __syncthreads();

    // Phase 2: transpose back to SP, XOR masks, accumulate next row parities
#pragma unroll 4
    for (int r = 0; r < 16; ++r) {
        int ii = warp * 16 + r;
        int i = i0 + ii;
        int mi = ii >> 2, b = ii & 3;
        uint32_t sel = (uint32_t)b | ((uint32_t)(b + 4) << 4);
        uint32_t w0 = sm[smidx(4 * lane + 0, mi)];
        uint32_t w1 = sm[smidx(4 * lane + 1, mi)];
        uint32_t w2 = sm[smidx(4 * lane + 2, mi)];
        uint32_t w3 = sm[smidx(4 * lane + 3, mi)];
        uint32_t t01 = __byte_perm(w0, w1, sel);
        uint32_t t23 = __byte_perm(w2, w3, sel);
        uint32_t out = __byte_perm(t01, t23, 0x5410);
        out ^= g_kcw[i & 1][wb + lane] ^ g_krw[i];
        g_SP[(p * 1024 + i) * WPR + wb + lane] = out;
        uint32_t red = warp_xor(out);
        if (lane == 0) atomicXor(&g_rp[nb][p * 1024 + i], red);
    }
}

// ---------------------------------------------------------------------------
// Unpack: packed bytes -> float / 255
// ---------------------------------------------------------------------------
__global__ void __launch_bounds__(256) k_unpack(float* __restrict__ out) {
    int idx = blockIdx.x * 256 + threadIdx.x;
    uint32_t w = g_SP[idx];
    const float s = 1.0f / 255.0f;
    float4 f;
    f.x = (float)(w & 255u) * s;
    f.y = (float)((w >> 8) & 255u) * s;
    f.z = (float)((w >> 16) & 255u) * s;
    f.w = (float)(w >> 24) * s;
    reinterpret_cast<float4*>(out)[idx] = f;
}

extern "C" void kernel_launch(void* const* d_in, const int* in_sizes, int n_in,
                              void* d_out, int out_size) {
    const float* x  = (const float*)d_in[0];
    const int*   kr = (const int*)d_in[1];
    const int*   kc = (const int*)d_in[2];
    const int*   it = (const int*)d_in[3];

    const int nwords = PLANES * HH * WPR;      // 12,582,912

    k_init<<<(NPW + 1023) / 1024, 1024>>>(kr, kc);
    k_pack<<<nwords / 256, 256>>>(x);

    dim3 grid(8, 8, PLANES);                   // 128x128-px tiles per plane
    for (int t = 0; t < 10; ++t) {             // iterations==10; kernels guard t >= *it
        k_row<<<grid, 256>>>(t, it);
        k_col<<<grid, 256>>>(t, it);
    }

    k_unpack<<<nwords / 256, 256>>>((float*)d_out);
}